// round 15
// baseline (speedup 1.0000x reference)
#include <cuda_runtime.h>

// SphericalBessel: two-pass outlier-aware scheme, counterless.
//
// Pass 1: all 2M elements in plain fp32 (3 FFMA/step Miller recurrence in
// the shrink-only scaled variable). Rows where the trajectory's y0 is within
// 3% of zero (normalization divides by y0 -> up to ~2e6 amplification) are
// flagged via a per-warp ballot word stored UNCONDITIONALLY to g_mask
// (overwrites stale data each replay: no counter, no reset kernel, no
// atomics, deterministic).
// Pass 2: one thread per mask word; reruns flagged elements (~2%) with the
// proven double-single core + accurate sincosf and overwrites their rows.

#define NPTS   65536
#define KMAX   32
#define LMAX   32
#define LSTART 49   // L_MAX + int(sqrt(10*L_MAX)) = 32 + 17
#define BLK    256
#define NWARPS (NPTS * KMAX / 32)        // 65536 pass-1 warps

__device__ unsigned g_mask[NWARPS];

// a + b and a - b as FFMA with immediate +-1.0 multiplier.
__device__ __forceinline__ float fa(float a, float b) {
    float d; asm("fma.rn.f32 %0,%1,0f3F800000,%2;" : "=f"(d) : "f"(a), "f"(b)); return d;
}
__device__ __forceinline__ float fs(float a, float b) {  // a - b
    float d; asm("fma.rn.f32 %0,%1,0fBF800000,%2;" : "=f"(d) : "f"(b), "f"(a)); return d;
}

// ---------------- Pass 1: fp32 everywhere + ballot flag ----------------
__global__ void __launch_bounds__(BLK)
sph_pass1(const float* __restrict__ r, float* __restrict__ out) {
    int tid = blockIdx.x * BLK + threadIdx.x;
    int n  = tid >> 5;
    int kk = tid & 31;                    // k = kk+1
    float kf = (float)(kk + 1);
    float rv = __ldg(&r[n]);

    float xh = rv * kf;
    float xl = fmaf(rv, kf, -xh);         // exact DS x (for sin phase comp)

    // sigma = 0.25 / 2^floor(log2 max(x,99))  (exact pow2)
    float m = fmaxf(xh, 99.0f);
    int pb = __float_as_int(m) & 0x7f800000;
    float sigma = __int_as_float(0x7E000000 - pb);

    float zh = xh * sigma;
    float nX2h = -(zh * zh);

    // fp32 recurrence: 3 ops/step (shrink-only, no overflow)
    float A = 0x1p70f, B = 0.0f;
    float y[LMAX];
    #pragma unroll
    for (int i = LSTART; i >= 1; --i) {
        float cs = (float)(2 * i + 1) * sigma;
        float C  = fmaf(nX2h, B, cs * A);
        B = A; A = C;
        if (i <= LMAX) y[i - 1] = C;
    }

    // danger flag: |y0| < 3% of local envelope (T_l = y_l * z^l; zeros of
    // successive j_l interlace, so the max over l=1..3 bounds the envelope)
    float t1 = fabsf(y[1]) * zh;
    float t2 = fabsf(y[2]) * zh;
    float t3 = fabsf(y[3]) * zh;
    float amp = fmaxf(t1, fmaxf(t2 * zh, t3 * zh * zh));
    bool danger = fabsf(y[0]) < 0.03f * amp;

    unsigned msk = __ballot_sync(0xffffffffu, danger);
    if ((threadIdx.x & 31) == 0)
        g_mask[tid >> 5] = msk;           // unconditional overwrite

    // normalization (fp32/MUFU; flagged rows overwritten by pass 2)
    float s, cc;
    __sincosf(xh, &s, &cc);
    s = fmaf(xl, cc, s);
    float norm = __fdividef(s * (0.7978845608028654f * kf), xh * y[0]);

    float zh2 = zh * zh;
    float ne = norm, no = norm * zh;
    float* o = out + (size_t)n * (LMAX * KMAX) + kk;
    #pragma unroll
    for (int l = 0; l < LMAX; l += 2) {
        o[(size_t)l * KMAX]       = y[l]     * ne;   // coalesced 128B per l
        o[(size_t)(l + 1) * KMAX] = y[l + 1] * no;
        ne *= zh2; no *= zh2;
    }
}

// ---------------- Pass 2: DS rerun of flagged elements ----------------
__global__ void __launch_bounds__(BLK)
sph_pass2(const float* __restrict__ r, float* __restrict__ out) {
    int w = blockIdx.x * BLK + threadIdx.x;   // one mask word per thread
    unsigned msk = g_mask[w];

    while (msk) {
        int lane = __ffs(msk) - 1;
        msk &= msk - 1;
        int id = w * 32 + lane;
        int n  = id >> 5;
        int kk = id & 31;
        float kf = (float)(kk + 1);
        float rv = __ldg(&r[n]);

        float xh = rv * kf;
        float xl = fmaf(rv, kf, -xh);

        float m = fmaxf(xh, 99.0f);
        int pb = __float_as_int(m) & 0x7f800000;
        float sigma = __int_as_float(0x7E000000 - pb);

        float zh = xh * sigma, zl = xl * sigma;
        float X2h = zh * zh;
        float X2l = fmaf(zh, zh, -X2h);
        X2l = fmaf(zh, 2.0f * zl, X2l);
        X2l = fmaf(zl, zl, X2l);

        float Ah = 0x1p70f, Al = 0.0f, Bh = 0.0f, Bl = 0.0f;
        float y[LMAX];
        float y0 = 0.0f;

        #pragma unroll
        for (int i = LSTART; i >= 1; --i) {
            float cs = (float)(2 * i + 1) * sigma;

            float th = cs * Ah;
            float te = fmaf(cs, Ah, -th);
            te = fmaf(cs, Al, te);

            float uh = X2h * Bh;
            float ue = fmaf(X2h, Bh, -uh);
            ue = fmaf(X2h, Bl, ue);
            ue = fmaf(X2l, Bh, ue);

            float sh = fs(th, uh);
            float v  = fs(sh, th);
            float ww = fs(sh, v);
            float e1 = fs(th, ww);
            float tt = fa(uh, v);
            float er = fs(e1, tt);
            float lo = fa(er, te);
            lo = fs(lo, ue);

            Bh = Ah; Bl = Al;
            Ah = sh; Al = lo;

            if (i == 1) y0 = fa(sh, lo);
            else if (i <= LMAX) y[i - 1] = sh;
        }
        y[0] = y0;

        // accurate normalization (full sincosf + DS phase compensation)
        float s, cc;
        sincosf(xh, &s, &cc);
        s = fmaf(xl, cc, s);
        float norm = (s / xh) * (0.7978845608028654f * kf) / y0;

        float zh2 = zh * zh;
        float ne = norm, no = norm * zh;
        float* o = out + (size_t)n * (LMAX * KMAX) + kk;
        #pragma unroll
        for (int l = 0; l < LMAX; l += 2) {
            o[(size_t)l * KMAX]       = y[l]     * ne;
            o[(size_t)(l + 1) * KMAX] = y[l + 1] * no;
            ne *= zh2; no *= zh2;
        }
    }
}

extern "C" void kernel_launch(void* const* d_in, const int* in_sizes, int n_in,
                              void* d_out, int out_size) {
    const float* r = (const float*)d_in[0];
    float* out = (float*)d_out;
    sph_pass1<<<NPTS * KMAX / BLK, BLK>>>(r, out);
    sph_pass2<<<NWARPS / BLK, BLK>>>(r, out);
}

// round 16
// speedup vs baseline: 1.1878x; 1.1878x over previous
#include <cuda_runtime.h>

// SphericalBessel: two-pass outlier-aware scheme.
//
// Pass 1 (~40us, at ~82% of HBM roofline): all 2M elements via plain fp32
// Miller recurrence (3 FFMA/step, shrink-only scaled variable). Rows whose
// trajectory y0 is within 3% of zero (the normalization divides by y0 ->
// up to ~2e6 amplification of trajectory error) are flagged via per-warp
// ballot words stored UNCONDITIONALLY to g_mask (replay-deterministic, no
// counter, no reset kernel).
// Pass 2 (~4us): 256 blocks; each block compacts its 256 mask words into a
// shared id list and reruns the flagged ~2% of elements with the proven
// double-single core + accurate sincosf — one parallel DS chain per thread.

#define NPTS   65536
#define KMAX   32
#define LMAX   32
#define LSTART 49   // L_MAX + int(sqrt(10*L_MAX)) = 32 + 17
#define BLK    256
#define NWARPS (NPTS * KMAX / 32)        // 65536 pass-1 warps / mask words
#define P2BLKS 256
#define WPB    (NWARPS / P2BLKS)         // 256 mask words per pass-2 block

__device__ unsigned g_mask[NWARPS];

// a + b and a - b as FFMA with immediate +-1.0 multiplier.
__device__ __forceinline__ float fa(float a, float b) {
    float d; asm("fma.rn.f32 %0,%1,0f3F800000,%2;" : "=f"(d) : "f"(a), "f"(b)); return d;
}
__device__ __forceinline__ float fs(float a, float b) {  // a - b
    float d; asm("fma.rn.f32 %0,%1,0fBF800000,%2;" : "=f"(d) : "f"(b), "f"(a)); return d;
}

// ---------------- Pass 1: fp32 everywhere + ballot flag ----------------
__global__ void __launch_bounds__(BLK)
sph_pass1(const float* __restrict__ r, float* __restrict__ out) {
    int tid = blockIdx.x * BLK + threadIdx.x;
    int n  = tid >> 5;
    int kk = tid & 31;                    // k = kk+1
    float kf = (float)(kk + 1);
    float rv = __ldg(&r[n]);

    float xh = rv * kf;
    float xl = fmaf(rv, kf, -xh);         // exact DS x (for sin phase comp)

    // sigma = 0.25 / 2^floor(log2 max(x,99))  (exact pow2)
    float m = fmaxf(xh, 99.0f);
    int pb = __float_as_int(m) & 0x7f800000;
    float sigma = __int_as_float(0x7E000000 - pb);

    float zh = xh * sigma;
    float nX2h = -(zh * zh);

    // fp32 recurrence: 3 ops/step (shrink-only, no overflow)
    float A = 0x1p70f, B = 0.0f;
    float y[LMAX];
    #pragma unroll
    for (int i = LSTART; i >= 1; --i) {
        float cs = (float)(2 * i + 1) * sigma;
        float C  = fmaf(nX2h, B, cs * A);
        B = A; A = C;
        if (i <= LMAX) y[i - 1] = C;
    }

    // danger flag: |y0| < 3% of local envelope (zeros of j_l interlace)
    float t1 = fabsf(y[1]) * zh;
    float t2 = fabsf(y[2]) * zh;
    float t3 = fabsf(y[3]) * zh;
    float amp = fmaxf(t1, fmaxf(t2 * zh, t3 * zh * zh));
    bool danger = fabsf(y[0]) < 0.03f * amp;

    unsigned msk = __ballot_sync(0xffffffffu, danger);
    if ((threadIdx.x & 31) == 0)
        g_mask[tid >> 5] = msk;           // unconditional overwrite

    // normalization (fp32/MUFU; flagged rows overwritten by pass 2)
    float s, cc;
    __sincosf(xh, &s, &cc);
    s = fmaf(xl, cc, s);
    float norm = __fdividef(s * (0.7978845608028654f * kf), xh * y[0]);

    float zh2 = zh * zh;
    float ne = norm, no = norm * zh;
    float* o = out + (size_t)n * (LMAX * KMAX) + kk;
    #pragma unroll
    for (int l = 0; l < LMAX; l += 2) {
        o[(size_t)l * KMAX]       = y[l]     * ne;   // coalesced 128B per l
        o[(size_t)(l + 1) * KMAX] = y[l + 1] * no;
        ne *= zh2; no *= zh2;
    }
}

// -------- Pass 2: block-local compaction + DS rerun of flagged ids --------
__global__ void __launch_bounds__(BLK)
sph_pass2(const float* __restrict__ r, float* __restrict__ out) {
    __shared__ int s_cnt;
    __shared__ int s_ids[WPB * 32];       // worst case: every bit set

    if (threadIdx.x == 0) s_cnt = 0;
    __syncthreads();

    // expand this block's 256 mask words into a shared id list
    int w = blockIdx.x * WPB + threadIdx.x;   // one word per thread
    unsigned msk = g_mask[w];
    while (msk) {
        int lane = __ffs(msk) - 1;
        msk &= msk - 1;
        int slot = atomicAdd(&s_cnt, 1);
        s_ids[slot] = w * 32 + lane;
    }
    __syncthreads();

    int cnt = s_cnt;
    for (int t = threadIdx.x; t < cnt; t += BLK) {
        int id = s_ids[t];
        int n  = id >> 5;
        int kk = id & 31;
        float kf = (float)(kk + 1);
        float rv = __ldg(&r[n]);

        float xh = rv * kf;
        float xl = fmaf(rv, kf, -xh);

        float m = fmaxf(xh, 99.0f);
        int pb = __float_as_int(m) & 0x7f800000;
        float sigma = __int_as_float(0x7E000000 - pb);

        float zh = xh * sigma, zl = xl * sigma;
        float X2h = zh * zh;
        float X2l = fmaf(zh, zh, -X2h);
        X2l = fmaf(zh, 2.0f * zl, X2l);
        X2l = fmaf(zl, zl, X2l);

        float Ah = 0x1p70f, Al = 0.0f, Bh = 0.0f, Bl = 0.0f;
        float y[LMAX];
        float y0 = 0.0f;

        #pragma unroll
        for (int i = LSTART; i >= 1; --i) {
            float cs = (float)(2 * i + 1) * sigma;

            float th = cs * Ah;
            float te = fmaf(cs, Ah, -th);
            te = fmaf(cs, Al, te);

            float uh = X2h * Bh;
            float ue = fmaf(X2h, Bh, -uh);
            ue = fmaf(X2h, Bl, ue);
            ue = fmaf(X2l, Bh, ue);

            float sh = fs(th, uh);
            float v  = fs(sh, th);
            float ww = fs(sh, v);
            float e1 = fs(th, ww);
            float tt = fa(uh, v);
            float er = fs(e1, tt);
            float lo = fa(er, te);
            lo = fs(lo, ue);

            Bh = Ah; Bl = Al;
            Ah = sh; Al = lo;

            if (i == 1) y0 = fa(sh, lo);
            else if (i <= LMAX) y[i - 1] = sh;
        }
        y[0] = y0;

        // accurate normalization (full sincosf + DS phase compensation)
        float s, cc;
        sincosf(xh, &s, &cc);
        s = fmaf(xl, cc, s);
        float norm = (s / xh) * (0.7978845608028654f * kf) / y0;

        float zh2 = zh * zh;
        float ne = norm, no = norm * zh;
        float* o = out + (size_t)n * (LMAX * KMAX) + kk;
        #pragma unroll
        for (int l = 0; l < LMAX; l += 2) {
            o[(size_t)l * KMAX]       = y[l]     * ne;
            o[(size_t)(l + 1) * KMAX] = y[l + 1] * no;
            ne *= zh2; no *= zh2;
        }
    }
}

extern "C" void kernel_launch(void* const* d_in, const int* in_sizes, int n_in,
                              void* d_out, int out_size) {
    const float* r = (const float*)d_in[0];
    float* out = (float*)d_out;
    sph_pass1<<<NPTS * KMAX / BLK, BLK>>>(r, out);
    sph_pass2<<<P2BLKS, BLK>>>(r, out);
}